// round 17
// baseline (speedup 1.0000x reference)
#include <cuda_runtime.h>
#include <cuda_fp16.h>
#include <math.h>
#include <stdint.h>

#define Bn 64
#define Tn 2048
#define Dn 256
#define Un 256

// ---- scratch (device globals, no allocation) ----
__device__ float d_score[Bn * Tn];         // pre-softmax scores
// W2 as fp16, chunk-major, smem-image layout: [8 chunks][256 rows][20 u32]
__device__ __align__(16) uint32_t d_W2h[8 * 256 * 20];

// ================= helpers =================
__device__ __forceinline__ uint32_t smem_u32(const void* p) {
    uint32_t a;
    asm("{ .reg .u64 t; cvta.to.shared.u64 t, %1; cvt.u32.u64 %0, t; }" : "=r"(a) : "l"(p));
    return a;
}
__device__ __forceinline__ void cp_async16(uint32_t dst, const void* src) {
    asm volatile("cp.async.ca.shared.global [%0], [%1], 16;" :: "r"(dst), "l"(src) : "memory");
}
__device__ __forceinline__ void cp_commit() {
    asm volatile("cp.async.commit_group;" ::: "memory");
}
template <int N>
__device__ __forceinline__ void cp_wait() {
    asm volatile("cp.async.wait_group %0;" :: "n"(N) : "memory");
}
__device__ __forceinline__ void mma_f16(float* c, const uint32_t* a, uint32_t b0, uint32_t b1) {
    asm volatile(
        "mma.sync.aligned.m16n8k16.row.col.f32.f16.f16.f32 "
        "{%0,%1,%2,%3}, {%4,%5,%6,%7}, {%8,%9}, {%0,%1,%2,%3};"
        : "+f"(c[0]), "+f"(c[1]), "+f"(c[2]), "+f"(c[3])
        : "r"(a[0]), "r"(a[1]), "r"(a[2]), "r"(a[3]), "r"(b0), "r"(b1));
}
#define LDSM_X4(r0, r1, r2, r3, addr) \
    asm volatile("ldmatrix.sync.aligned.m8n8.x4.shared.b16 {%0,%1,%2,%3}, [%4];" \
                 : "=r"(r0), "=r"(r1), "=r"(r2), "=r"(r3) : "r"(addr))
__device__ __forceinline__ uint32_t pack_h2(float lo, float hi) {
    __half2 h = __floats2half2_rn(lo, hi);   // .x = lo
    return *(uint32_t*)&h;
}
static __device__ __forceinline__ float tanh_fast(float x) {
    float r;
    asm("tanh.approx.f32 %0, %1;" : "=f"(r) : "f"(x));
    return r;
}

// ============================================================
// Kernel 0: prep — W2h build (0..63) + ctx-zero of out (64..79)
// ============================================================
__global__ void prep_kernel(const float* __restrict__ W2w,
                            float* __restrict__ out) {
    if (blockIdx.x < 64) {
        // W2h build: block -> (chunk c, urow group); lane <-> consecutive urow
        int bid = blockIdx.x;                 // 0..63
        int c = bid >> 3, ug = bid & 7;
        int lane = threadIdx.x & 31, qi = threadIdx.x >> 5;   // qi 0..7
        int urow = ug * 32 + lane;
        int k0 = c * 32 + 4 * qi;
        uint32_t w0 = pack_h2(W2w[(size_t)(k0 + 0) * Un + urow],
                              W2w[(size_t)(k0 + 1) * Un + urow]);
        uint32_t w1 = pack_h2(W2w[(size_t)(k0 + 2) * Un + urow],
                              W2w[(size_t)(k0 + 3) * Un + urow]);
        *(uint2*)&d_W2h[(c * 256 + urow) * 20 + 2 * qi] = make_uint2(w0, w1);
    } else {
        // zero context-vector region of out (16 blocks x 256 threads x float4)
        int id = (blockIdx.x - 64) * 256 + threadIdx.x;   // 0..4095
        ((float4*)out)[id] = make_float4(0.f, 0.f, 0.f, 0.f);
    }
}

// ============================================================
// Kernel 2: fp16 mma.sync GEMM (128 x 256 x 256) + tanh + dot(Vw)
// R12 mainloop + qproj folded in (32 FMA + 36 LDG per chunk on idle pipes;
// qs consumed only in epilogue, so the latency is hidden under the GEMM).
// ============================================================
#define ST 20                       // uint32 stride per row (16 data + 4 pad)
#define A_ROWS 128
#define A_U32 (A_ROWS * ST)         // 2560 per buffer
#define B_U32 (256 * ST)            // 5120 per buffer
#define SC_SMEM (2 * (A_U32 + B_U32) * 4)   // 61440 B

__global__ __launch_bounds__(256, 1)
void score_kernel(const float* __restrict__ values,
                  const float* __restrict__ query,
                  const float* __restrict__ W1w,
                  const float* __restrict__ W1b,
                  const float* __restrict__ W2b,
                  const float* __restrict__ Vw,
                  const float* __restrict__ Vb) {
    extern __shared__ __align__(16) uint32_t su[];
    uint32_t* Abuf = su;                 // 2 x A_U32
    uint32_t* Bbuf = su + 2 * A_U32;     // 2 x B_U32
    __shared__ float qs[Un];
    __shared__ float vs[Un];
    __shared__ float sp[A_ROWS * 4];

    const int tid = threadIdx.x;
    const int wid = tid >> 5;
    const int lane = tid & 31;
    const int g = lane >> 2;
    const int tg = lane & 3;
    const int mw = wid >> 2;       // 0..1  (row half)
    const int nw = wid & 3;        // 0..3  (col quarter)
    const int r0 = blockIdx.x * A_ROWS;
    const int b = r0 >> 11;

    vs[tid] = Vw[tid];
    float qa0 = W1b[tid] + W2b[tid];   // qproj accumulator (u = tid)
    float qa1 = 0.f;

    const int arow = tid >> 3;
    const int kq = tid & 7;

    const int lr = lane & 7;
    const int lh = (lane >> 3) & 1;
    const int lk = (lane >> 4) & 1;

    const uint32_t abase = smem_u32(Abuf);
    const uint32_t bbase = smem_u32(Bbuf);

    uint32_t aoff[4];
#pragma unroll
    for (int i = 0; i < 4; i++)
        aoff[i] = (uint32_t)(((mw * 64 + i * 16 + lr + lh * 8) * ST + lk * 4) * 4);
    uint32_t boff[4];
#pragma unroll
    for (int jp = 0; jp < 4; jp++)
        boff[jp] = (uint32_t)(((nw * 64 + jp * 16 + lr + lk * 8) * ST + lh * 4) * 4);

    float4 pa[4];

    auto ldg_a = [&](int c) {
        const int kc = c * 32;
        const float* agp = values + (size_t)r0 * Dn + kc + kq * 4;
#pragma unroll
        for (int it = 0; it < 4; it++)
            pa[it] = *(const float4*)(agp + (size_t)(arow + it * 32) * Dn);
    };
    auto cp_b = [&](int c, int buf) {
        const uint32_t* src = d_W2h + c * B_U32;
        uint32_t dstb = bbase + (uint32_t)(buf * B_U32 * 4);
#pragma unroll
        for (int it = 0; it < 5; it++) {
            int s = tid + it * 256;
            cp_async16(dstb + s * 16, src + s * 4);
        }
        cp_commit();
    };
    auto sts_a = [&](int buf) {
        uint32_t* Ad = Abuf + buf * A_U32;
#pragma unroll
        for (int it = 0; it < 4; it++) {
            int row = arow + it * 32;
            *(uint2*)&Ad[row * ST + kq * 2] =
                make_uint2(pack_h2(pa[it].x, pa[it].y), pack_h2(pa[it].z, pa[it].w));
        }
    };

    float acc[4][8][4];
#pragma unroll
    for (int i = 0; i < 4; i++)
#pragma unroll
        for (int j = 0; j < 8; j++)
#pragma unroll
            for (int q = 0; q < 4; q++) acc[i][j][q] = 0.f;

    ldg_a(0);
    cp_b(0, 0);
    sts_a(0);
    cp_wait<0>();
    __syncthreads();

#pragma unroll 1
    for (int c = 0; c < 8; c++) {
        if (c < 7) { ldg_a(c + 1); cp_b(c + 1, (c + 1) & 1); }

        const uint32_t au_b = abase + (uint32_t)((c & 1) * A_U32 * 4);
        const uint32_t bu_b = bbase + (uint32_t)((c & 1) * B_U32 * 4);

#pragma unroll
        for (int ks = 0; ks < 2; ks++) {
            const uint32_t kbyte = ks * 32;
            uint32_t afr[4][4];
#pragma unroll
            for (int i = 0; i < 4; i++)
                LDSM_X4(afr[i][0], afr[i][1], afr[i][2], afr[i][3], au_b + aoff[i] + kbyte);
#pragma unroll
            for (int jp = 0; jp < 4; jp++) {
                uint32_t b00, b01, b10, b11;
                LDSM_X4(b00, b01, b10, b11, bu_b + boff[jp] + kbyte);
#pragma unroll
                for (int i = 0; i < 4; i++) {
                    mma_f16(acc[i][jp * 2], afr[i], b00, b01);
                    mma_f16(acc[i][jp * 2 + 1], afr[i], b10, b11);
                }
            }
        }

        // ---- interleaved qproj slice: 32 d's on the idle fma/LSU pipes ----
        {
            const float* w1c = W1w + (size_t)(c * 32) * Un + tid;
            const float* qv = query + b * Dn + c * 32;
#pragma unroll
            for (int d = 0; d < 32; d += 2) {
                qa0 = fmaf(__ldg(qv + d),     w1c[(size_t)d * Un],       qa0);
                qa1 = fmaf(__ldg(qv + d + 1), w1c[(size_t)(d + 1) * Un], qa1);
            }
        }

        if (c < 7) { sts_a((c + 1) & 1); cp_wait<0>(); }
        __syncthreads();
    }

    // publish qproj result for epilogue
    qs[tid] = qa0 + qa1;
    __syncthreads();

    // ---- epilogue: p[row] = sum_u tanh(acc + qs[u]) * vs[u] ----
    float p[4][2];
#pragma unroll
    for (int i = 0; i < 4; i++) { p[i][0] = 0.f; p[i][1] = 0.f; }

#pragma unroll
    for (int j = 0; j < 8; j++) {
        int u0 = nw * 64 + j * 8 + 2 * tg;
        int u1 = u0 + 1;
        float q0 = qs[u0], q1 = qs[u1], v0 = vs[u0], v1 = vs[u1];
#pragma unroll
        for (int i = 0; i < 4; i++) {
            p[i][0] = fmaf(tanh_fast(acc[i][j][0] + q0), v0, p[i][0]);
            p[i][0] = fmaf(tanh_fast(acc[i][j][1] + q1), v1, p[i][0]);
            p[i][1] = fmaf(tanh_fast(acc[i][j][2] + q0), v0, p[i][1]);
            p[i][1] = fmaf(tanh_fast(acc[i][j][3] + q1), v1, p[i][1]);
        }
    }
#pragma unroll
    for (int off = 1; off < 4; off <<= 1)
#pragma unroll
        for (int i = 0; i < 4; i++) {
            p[i][0] += __shfl_xor_sync(0xffffffffu, p[i][0], off);
            p[i][1] += __shfl_xor_sync(0xffffffffu, p[i][1], off);
        }
    if (tg == 0) {
#pragma unroll
        for (int i = 0; i < 4; i++) {
            sp[(mw * 64 + i * 16 + g) * 4 + nw] = p[i][0];
            sp[(mw * 64 + i * 16 + g + 8) * 4 + nw] = p[i][1];
        }
    }
    __syncthreads();
    if (tid < A_ROWS) {
        float s = sp[tid * 4] + sp[tid * 4 + 1] + sp[tid * 4 + 2] + sp[tid * 4 + 3];
        d_score[r0 + tid] = s + Vb[0];
    }
}

// ============================================================
// Kernel 4: weights + context (grid = B*16, 128-t chunks)
// Inline per-block softmax stats (scores L2-resident), context via atomics.
// ============================================================
__global__ void weights_ctx_kernel(const float* __restrict__ values,
                                   float* __restrict__ out) {
    int b = blockIdx.x >> 4;
    int ch = blockIdx.x & 15;
    int tid = threadIdx.x;
    __shared__ float sw[128];
    __shared__ float4 red[256];
    __shared__ float rm[8], rs[8];
    __shared__ float s_mv, s_den;

    // ---- inline softmax stats over this b's 2048 scores ----
    {
        const float4* sc = (const float4*)(d_score + b * Tn);
        float4 v1 = sc[tid], v2 = sc[tid + 256];
        float m = fmaxf(fmaxf(fmaxf(v1.x, v1.y), fmaxf(v1.z, v1.w)),
                        fmaxf(fmaxf(v2.x, v2.y), fmaxf(v2.z, v2.w)));
        float s = __expf(v1.x - m) + __expf(v1.y - m) + __expf(v1.z - m) + __expf(v1.w - m)
                + __expf(v2.x - m) + __expf(v2.y - m) + __expf(v2.z - m) + __expf(v2.w - m);
#pragma unroll
        for (int o = 16; o > 0; o >>= 1) {
            float m2 = __shfl_xor_sync(0xffffffffu, m, o);
            float s2 = __shfl_xor_sync(0xffffffffu, s, o);
            float mn = fmaxf(m, m2);
            s = s * __expf(m - mn) + s2 * __expf(m2 - mn);
            m = mn;
        }
        if ((tid & 31) == 0) { rm[tid >> 5] = m; rs[tid >> 5] = s; }
        __syncthreads();
        if (tid < 32) {
            float mm = (tid < 8) ? rm[tid] : -1e30f;
            float ss = (tid < 8) ? rs[tid] : 0.f;
#pragma unroll
            for (int o = 4; o > 0; o >>= 1) {
                float m2 = __shfl_xor_sync(0xffffffffu, mm, o);
                float s2 = __shfl_xor_sync(0xffffffffu, ss, o);
                float mn = fmaxf(mm, m2);
                ss = ss * __expf(mm - mn) + s2 * __expf(m2 - mn);
                mm = mn;
            }
            if (tid == 0) { s_mv = mm; s_den = ss; }
        }
        __syncthreads();
    }

    if (tid < 128) {
        int t = ch * 128 + tid;
        float w = __expf(d_score[b * Tn + t] - s_mv) / s_den;
        out[Bn * Dn + b * Tn + t] = w;
        sw[tid] = w;
    }
    __syncthreads();

    int rg = tid >> 6, dg = tid & 63;      // 4 row groups x 32 rows
    const float4* vp = (const float4*)(values + (size_t)(b * Tn + ch * 128 + rg * 32) * Dn) + dg;
    float4 acc = make_float4(0.f, 0.f, 0.f, 0.f);
#pragma unroll 8
    for (int tt = 0; tt < 32; tt++) {
        float w = sw[rg * 32 + tt];
        float4 v = vp[(size_t)tt * 64];
        acc.x = fmaf(w, v.x, acc.x);
        acc.y = fmaf(w, v.y, acc.y);
        acc.z = fmaf(w, v.z, acc.z);
        acc.w = fmaf(w, v.w, acc.w);
    }
    red[tid] = acc;
    __syncthreads();
    if (tid < 64) {
        float4 a = red[tid], b1 = red[64 + tid], c = red[128 + tid], d = red[192 + tid];
        a.x += b1.x + c.x + d.x;
        a.y += b1.y + c.y + d.y;
        a.z += b1.z + c.z + d.z;
        a.w += b1.w + c.w + d.w;
        float* op = out + b * Dn + tid * 4;
        atomicAdd(op + 0, a.x);
        atomicAdd(op + 1, a.y);
        atomicAdd(op + 2, a.z);
        atomicAdd(op + 3, a.w);
    }
}

// ============================================================
extern "C" void kernel_launch(void* const* d_in, const int* in_sizes, int n_in,
                              void* d_out, int out_size) {
    const float* query = (const float*)d_in[0];
    const float* values = (const float*)d_in[1];
    const float* W1w = (const float*)d_in[2];
    const float* W1b = (const float*)d_in[3];
    const float* W2w = (const float*)d_in[4];
    const float* W2b = (const float*)d_in[5];
    const float* Vw  = (const float*)d_in[6];
    const float* Vb  = (const float*)d_in[7];
    float* out = (float*)d_out;

    static int smem_set = 0;
    if (!smem_set) {
        cudaFuncSetAttribute(score_kernel, cudaFuncAttributeMaxDynamicSharedMemorySize, SC_SMEM);
        smem_set = 1;
    }

    prep_kernel<<<80, 256>>>(W2w, out);
    score_kernel<<<(Bn * Tn) / A_ROWS, 256, SC_SMEM>>>(values, query, W1w, W1b, W2b, Vw, Vb);
    weights_ctx_kernel<<<Bn * 16, 256>>>(values, out);
}